// round 12
// baseline (speedup 1.0000x reference)
#include <cuda_runtime.h>
#include <cstdint>
#include <cstddef>

// Problem constants
#define T_   800
#define B_   32
#define D_   440
#define DP_  448      // D padded to multiple of 32
#define H_   1024
#define HH_  2048     // 2*H
#define L_   4
#define O_   2000
#define OP_  2048     // O padded to multiple of 128
#define M_   25600    // T*B
#define EPS_ 1e-5f

// ---------------- device-global scratch (allowed; zero-initialized) ----------------
__device__ float g_A0[M_ * DP_];          // padded+tf32-rounded xs          (45.9 MB)
__device__ float g_W0[HH_ * DP_];         // padded+rounded w0               ( 3.7 MB)
__device__ float g_Wr[3 * HH_ * H_];      // rounded wr                      (25.2 MB)
__device__ float g_Wf[OP_ * H_];          // rounded wf, rows >=2000 zero    ( 8.4 MB)
__device__ float g_Z[M_ * H_];            // sigmoid(BN(wz))                 (104.9 MB)
__device__ float g_C[M_ * H_];            // relu(BN(wc))                    (104.9 MB)
__device__ float g_X[M_ * H_];            // layer output (tf32-rounded)     (104.9 MB)
__device__ float g_zs[L_ * H_], g_zb[L_ * H_];
__device__ float g_cs[L_ * H_], g_cb[L_ * H_];
__device__ float g_fs[O_], g_fb[O_];

__device__ __forceinline__ float tf32r(float x) {
    uint32_t u;
    asm("cvt.rna.tf32.f32 %0, %1;" : "=r"(u) : "f"(x));
    return __uint_as_float(u);
}

// ---------------- prep kernels: pad + round-to-tf32 + BN fold ----------------
__global__ void prep_x(const float* __restrict__ xs) {
    int i = blockIdx.x * 256 + threadIdx.x;
    if (i >= M_ * DP_) return;
    int row = i / DP_, col = i - row * DP_;
    float v = (col < D_) ? xs[(size_t)row * D_ + col] : 0.0f;
    g_A0[i] = tf32r(v);
}
__global__ void prep_w0(const float* __restrict__ w) {
    int i = blockIdx.x * 256 + threadIdx.x;
    if (i >= HH_ * DP_) return;
    int row = i / DP_, col = i - row * DP_;
    float v = (col < D_) ? w[(size_t)row * D_ + col] : 0.0f;
    g_W0[i] = tf32r(v);
}
__global__ void prep_wr(const float* __restrict__ w) {
    int i = blockIdx.x * 256 + threadIdx.x;
    if (i >= 3 * HH_ * H_) return;
    g_Wr[i] = tf32r(w[i]);
}
__global__ void prep_wf(const float* __restrict__ w) {
    int i = blockIdx.x * 256 + threadIdx.x;
    if (i >= OP_ * H_) return;
    int row = i / H_, col = i - row * H_;
    g_Wf[i] = (row < O_) ? tf32r(w[(size_t)row * H_ + col]) : 0.0f;
}
__global__ void prep_bn(const float* __restrict__ zg, const float* __restrict__ zb,
                        const float* __restrict__ zm, const float* __restrict__ zv,
                        const float* __restrict__ cg, const float* __restrict__ cb,
                        const float* __restrict__ cm, const float* __restrict__ cv,
                        const float* __restrict__ fg, const float* __restrict__ fb,
                        const float* __restrict__ fm, const float* __restrict__ fv) {
    int i = blockIdx.x * 256 + threadIdx.x;
    if (i < L_ * H_) {
        float s = zg[i] * rsqrtf(zv[i] + EPS_);
        g_zs[i] = s; g_zb[i] = zb[i] - zm[i] * s;
        float s2 = cg[i] * rsqrtf(cv[i] + EPS_);
        g_cs[i] = s2; g_cb[i] = cb[i] - cm[i] * s2;
    }
    if (i < O_) {
        float s = fg[i] * rsqrtf(fv[i] + EPS_);
        g_fs[i] = s; g_fb[i] = fb[i] - fm[i] * s;
    }
}

// ---------------- GEMM: C[M,N] = A[M,K] * B[N,K]^T  (tf32 mma.sync) ----------------
// CTA tile 128x128x32, 3-stage cp.async pipeline, 8 warps (2m x 4n), warp tile 64x32.
// Shared memory per stage: A 128x32 f32 (16KB) + B 128x32 f32 (16KB). XOR-swizzled
// in 16B chunks: chunk' = chunk ^ (row & 7) -> conflict-free ldmatrix & stores.

__device__ __forceinline__ void g_load_stage(uint32_t smemBase, int s, int kt,
                                             const float* __restrict__ A,
                                             const float* __restrict__ Bw,
                                             int K, int mBase, int nBase, int tid) {
    uint32_t aS = smemBase + (uint32_t)s * 32768u;
    uint32_t bS = aS + 16384u;
#pragma unroll
    for (int i = 0; i < 4; ++i) {
        int chunk = tid + (i << 8);             // 0..1023
        int row = chunk >> 3;
        int c = chunk & 7;
        const float* src = A + (size_t)(mBase + row) * (size_t)K + (size_t)(kt * 32 + (c << 2));
        uint32_t dst = aS + (uint32_t)((row << 7) + ((c ^ (row & 7)) << 4));
        asm volatile("cp.async.cg.shared.global [%0], [%1], 16;\n" :: "r"(dst), "l"(src) : "memory");
    }
#pragma unroll
    for (int i = 0; i < 4; ++i) {
        int chunk = tid + (i << 8);
        int row = chunk >> 3;
        int c = chunk & 7;
        const float* src = Bw + (size_t)(nBase + row) * (size_t)K + (size_t)(kt * 32 + (c << 2));
        uint32_t dst = bS + (uint32_t)((row << 7) + ((c ^ (row & 7)) << 4));
        asm volatile("cp.async.cg.shared.global [%0], [%1], 16;\n" :: "r"(dst), "l"(src) : "memory");
    }
}

template <bool FINAL>
__global__ void __launch_bounds__(256, 2)
gemm_kernel(int selA, int selB, int wOff, int K, int paramOff, float* __restrict__ outF) {
    extern __shared__ float smem[];
    const float* __restrict__ A = selA ? g_X : g_A0;
    const float* __restrict__ Bw = (selB == 0) ? g_W0 : ((selB == 1) ? (g_Wr + wOff) : g_Wf);

    const int tid  = threadIdx.x;
    const int lane = tid & 31;
    const int warp = tid >> 5;
    const int wm = warp & 1;       // 0..1  (m direction, 64 rows each)
    const int wn = warp >> 1;      // 0..3  (n direction, 32 cols each)
    const int mBase = blockIdx.y * 128;
    const int nBase = blockIdx.x * 128;

    uint32_t smemBase = (uint32_t)__cvta_generic_to_shared(smem);

    float acc[4][4][4];
#pragma unroll
    for (int mi = 0; mi < 4; ++mi)
#pragma unroll
        for (int ni = 0; ni < 4; ++ni)
#pragma unroll
            for (int e = 0; e < 4; ++e) acc[mi][ni][e] = 0.0f;

    const int NK = K >> 5;   // >= 14 always

    g_load_stage(smemBase, 0, 0, A, Bw, K, mBase, nBase, tid);
    asm volatile("cp.async.commit_group;\n" ::: "memory");
    g_load_stage(smemBase, 1, 1, A, Bw, K, mBase, nBase, tid);
    asm volatile("cp.async.commit_group;\n" ::: "memory");

    const int q = lane >> 3;      // 0..3 (ldmatrix sub-matrix index)
    const int r = lane & 7;

    for (int kt = 0; kt < NK; ++kt) {
        if (kt + 1 < NK) { asm volatile("cp.async.wait_group 1;\n" ::: "memory"); }
        else            { asm volatile("cp.async.wait_group 0;\n" ::: "memory"); }
        __syncthreads();

        if (kt + 2 < NK) {
            g_load_stage(smemBase, (kt + 2) % 3, kt + 2, A, Bw, K, mBase, nBase, tid);
            asm volatile("cp.async.commit_group;\n" ::: "memory");
        }

        uint32_t aS = smemBase + (uint32_t)((kt % 3) * 32768);
        uint32_t bS = aS + 16384u;

#pragma unroll
        for (int kk = 0; kk < 4; ++kk) {
            uint32_t af[4][4];
#pragma unroll
            for (int mi = 0; mi < 4; ++mi) {
                int m0 = wm * 64 + mi * 16;
                int mrow = m0 + r + ((q & 1) << 3);
                int ch = 2 * kk + (q >> 1);
                uint32_t addr = aS + (uint32_t)((mrow << 7) + ((ch ^ (mrow & 7)) << 4));
                asm volatile("ldmatrix.sync.aligned.m8n8.x4.shared.b16 {%0,%1,%2,%3}, [%4];\n"
                             : "=r"(af[mi][0]), "=r"(af[mi][1]), "=r"(af[mi][2]), "=r"(af[mi][3])
                             : "r"(addr));
            }
            uint32_t bf[4][2];
#pragma unroll
            for (int p = 0; p < 2; ++p) {
                int ni = p * 2 + (q >> 1);
                int nrow = wn * 32 + ni * 8 + r;
                int ch = 2 * kk + (q & 1);
                uint32_t addr = bS + (uint32_t)((nrow << 7) + ((ch ^ (nrow & 7)) << 4));
                asm volatile("ldmatrix.sync.aligned.m8n8.x4.shared.b16 {%0,%1,%2,%3}, [%4];\n"
                             : "=r"(bf[p * 2][0]), "=r"(bf[p * 2][1]),
                               "=r"(bf[p * 2 + 1][0]), "=r"(bf[p * 2 + 1][1])
                             : "r"(addr));
            }
#pragma unroll
            for (int mi = 0; mi < 4; ++mi)
#pragma unroll
                for (int ni = 0; ni < 4; ++ni) {
                    asm volatile(
                        "mma.sync.aligned.m16n8k8.row.col.f32.tf32.tf32.f32 "
                        "{%0,%1,%2,%3}, {%4,%5,%6,%7}, {%8,%9}, {%0,%1,%2,%3};\n"
                        : "+f"(acc[mi][ni][0]), "+f"(acc[mi][ni][1]),
                          "+f"(acc[mi][ni][2]), "+f"(acc[mi][ni][3])
                        : "r"(af[mi][0]), "r"(af[mi][1]), "r"(af[mi][2]), "r"(af[mi][3]),
                          "r"(bf[ni][0]), "r"(bf[ni][1]));
                }
        }
    }

    // ---------------- fused epilogue ----------------
    const int gg = lane >> 2;
    const int tt = lane & 3;
#pragma unroll
    for (int mi = 0; mi < 4; ++mi) {
#pragma unroll
        for (int ni = 0; ni < 4; ++ni) {
            int row = mBase + wm * 64 + mi * 16 + gg;
            int col = nBase + wn * 32 + ni * 8 + 2 * tt;
#pragma unroll
            for (int e = 0; e < 4; ++e) {
                int rr = row + ((e >= 2) ? 8 : 0);
                int cc = col + (e & 1);
                float v = acc[mi][ni][e];
                if (FINAL) {
                    if (cc < O_) outF[(size_t)rr * O_ + cc] = g_fs[cc] * v + g_fb[cc];
                } else {
                    if (cc < H_) {
                        float x = g_zs[paramOff + cc] * v + g_zb[paramOff + cc];
                        g_Z[(size_t)rr * H_ + cc] = 1.0f / (1.0f + __expf(-x));
                    } else {
                        int c2 = cc - H_;
                        float x = g_cs[paramOff + c2] * v + g_cb[paramOff + c2];
                        g_C[(size_t)rr * H_ + c2] = fmaxf(x, 0.0f);
                    }
                }
            }
        }
    }
}

// ---------------- recurrence scan: elementwise over (b,h), sequential in t ----------------
__global__ void scan_kernel() {
    int e = blockIdx.x * blockDim.x + threadIdx.x;   // 0..32767  (= b*H + h)
    float h = 0.0f;
    size_t idx = (size_t)e;
#pragma unroll 8
    for (int t = 0; t < T_; ++t) {
        float z = g_Z[idx];
        float c = g_C[idx];
        h = (1.0f - z) * c + z * h;
        g_X[idx] = tf32r(h);
        idx += (size_t)(B_ * H_);
    }
}

// ---------------- row-wise log_softmax over O=2000, in place ----------------
__global__ void lsm_kernel(float* __restrict__ out) {
    const int rrow = blockIdx.x;
    float* p = out + (size_t)rrow * O_;
    __shared__ float sm1[8];
    __shared__ float sm2[8];
    const int tid = threadIdx.x;

    float mx = -1e30f;
    for (int o = tid; o < O_; o += 256) mx = fmaxf(mx, p[o]);
#pragma unroll
    for (int off = 16; off; off >>= 1) mx = fmaxf(mx, __shfl_xor_sync(0xffffffffu, mx, off));
    if ((tid & 31) == 0) sm1[tid >> 5] = mx;
    __syncthreads();
    float bm = fmaxf(fmaxf(fmaxf(sm1[0], sm1[1]), fmaxf(sm1[2], sm1[3])),
                     fmaxf(fmaxf(sm1[4], sm1[5]), fmaxf(sm1[6], sm1[7])));

    float s = 0.0f;
    for (int o = tid; o < O_; o += 256) s += __expf(p[o] - bm);
#pragma unroll
    for (int off = 16; off; off >>= 1) s += __shfl_xor_sync(0xffffffffu, s, off);
    if ((tid & 31) == 0) sm2[tid >> 5] = s;
    __syncthreads();
    float bs = sm2[0] + sm2[1] + sm2[2] + sm2[3] + sm2[4] + sm2[5] + sm2[6] + sm2[7];

    float lse = bm + logf(bs);
    for (int o = tid; o < O_; o += 256) p[o] = p[o] - lse;
}

// ---------------- launch ----------------
extern "C" void kernel_launch(void* const* d_in, const int* in_sizes, int n_in,
                              void* d_out, int out_size) {
    (void)in_sizes; (void)n_in; (void)out_size;
    const float* xs    = (const float*)d_in[0];
    const float* w0    = (const float*)d_in[1];
    const float* wr    = (const float*)d_in[2];
    const float* bnz_g = (const float*)d_in[3];
    const float* bnz_b = (const float*)d_in[4];
    const float* bnz_m = (const float*)d_in[5];
    const float* bnz_v = (const float*)d_in[6];
    const float* bnc_g = (const float*)d_in[7];
    const float* bnc_b = (const float*)d_in[8];
    const float* bnc_m = (const float*)d_in[9];
    const float* bnc_v = (const float*)d_in[10];
    const float* wf    = (const float*)d_in[11];
    const float* bnf_g = (const float*)d_in[12];
    const float* bnf_b = (const float*)d_in[13];
    const float* bnf_m = (const float*)d_in[14];
    const float* bnf_v = (const float*)d_in[15];
    float* out = (float*)d_out;

    const int SMEM = 98304;   // 3 stages * 32KB
    cudaFuncSetAttribute(gemm_kernel<false>, cudaFuncAttributeMaxDynamicSharedMemorySize, SMEM);
    cudaFuncSetAttribute(gemm_kernel<true>,  cudaFuncAttributeMaxDynamicSharedMemorySize, SMEM);

    prep_x <<<(M_ * DP_ + 255) / 256, 256>>>(xs);
    prep_w0<<<(HH_ * DP_ + 255) / 256, 256>>>(w0);
    prep_wr<<<(3 * HH_ * H_ + 255) / 256, 256>>>(wr);
    prep_wf<<<(OP_ * H_ + 255) / 256, 256>>>(wf);
    prep_bn<<<16, 256>>>(bnz_g, bnz_b, bnz_m, bnz_v,
                         bnc_g, bnc_b, bnc_m, bnc_v,
                         bnf_g, bnf_b, bnf_m, bnf_v);

    dim3 grid(16, 200);   // N/128, M/128

    // layer 0: A = padded xs (K=448), B = padded w0
    gemm_kernel<false><<<grid, 256, SMEM>>>(0, 0, 0, DP_, 0, nullptr);
    scan_kernel<<<128, 256>>>();

    // layers 1..3: A = X (K=1024), B = wr[i-1]
    for (int i = 1; i < L_; ++i) {
        gemm_kernel<false><<<grid, 256, SMEM>>>(1, 1, (i - 1) * HH_ * H_, H_, i * H_, nullptr);
        scan_kernel<<<128, 256>>>();
    }

    // final: logits = X @ wf^T with fused BN, then log_softmax in place
    gemm_kernel<true><<<grid, 256, SMEM>>>(1, 2, 0, H_, 0, out);
    lsm_kernel<<<M_, 256>>>(out);
}

// round 13
// speedup vs baseline: 1.0003x; 1.0003x over previous
#include <cuda_runtime.h>
#include <cstdint>
#include <cstddef>

// Problem constants
#define T_   800
#define B_   32
#define D_   440
#define DP_  448      // D padded to multiple of 32
#define H_   1024
#define HH_  2048     // 2*H
#define L_   4
#define O_   2000
#define OP_  2048     // O padded to multiple of 128
#define M_   25600    // T*B
#define EPS_ 1e-5f

// ---------------- device-global scratch (allowed; zero-initialized) ----------------
__device__ float g_A0[M_ * DP_];          // padded+tf32-rounded xs          (45.9 MB)
__device__ float g_W0[HH_ * DP_];         // padded+rounded w0               ( 3.7 MB)
__device__ float g_Wr[3 * HH_ * H_];      // rounded wr                      (25.2 MB)
__device__ float g_Wf[OP_ * H_];          // rounded wf, rows >=2000 zero    ( 8.4 MB)
__device__ float g_Z[M_ * H_];            // sigmoid(BN(wz))                 (104.9 MB)
__device__ float g_C[M_ * H_];            // relu(BN(wc))                    (104.9 MB)
__device__ float g_X[M_ * H_];            // layer output (tf32-rounded)     (104.9 MB)
__device__ float g_zs[L_ * H_], g_zb[L_ * H_];
__device__ float g_cs[L_ * H_], g_cb[L_ * H_];
__device__ float g_fs[O_], g_fb[O_];

__device__ __forceinline__ float tf32r(float x) {
    uint32_t u;
    asm("cvt.rna.tf32.f32 %0, %1;" : "=r"(u) : "f"(x));
    return __uint_as_float(u);
}

// ---------------- prep kernels: pad + round-to-tf32 + BN fold ----------------
__global__ void prep_x(const float* __restrict__ xs) {
    int i = blockIdx.x * 256 + threadIdx.x;
    if (i >= M_ * DP_) return;
    int row = i / DP_, col = i - row * DP_;
    float v = (col < D_) ? xs[(size_t)row * D_ + col] : 0.0f;
    g_A0[i] = tf32r(v);
}
__global__ void prep_w0(const float* __restrict__ w) {
    int i = blockIdx.x * 256 + threadIdx.x;
    if (i >= HH_ * DP_) return;
    int row = i / DP_, col = i - row * DP_;
    float v = (col < D_) ? w[(size_t)row * D_ + col] : 0.0f;
    g_W0[i] = tf32r(v);
}
__global__ void prep_wr(const float* __restrict__ w) {
    int i = blockIdx.x * 256 + threadIdx.x;
    if (i >= 3 * HH_ * H_) return;
    g_Wr[i] = tf32r(w[i]);
}
__global__ void prep_wf(const float* __restrict__ w) {
    int i = blockIdx.x * 256 + threadIdx.x;
    if (i >= OP_ * H_) return;
    int row = i / H_, col = i - row * H_;
    g_Wf[i] = (row < O_) ? tf32r(w[(size_t)row * H_ + col]) : 0.0f;
}
__global__ void prep_bn(const float* __restrict__ zg, const float* __restrict__ zb,
                        const float* __restrict__ zm, const float* __restrict__ zv,
                        const float* __restrict__ cg, const float* __restrict__ cb,
                        const float* __restrict__ cm, const float* __restrict__ cv,
                        const float* __restrict__ fg, const float* __restrict__ fb,
                        const float* __restrict__ fm, const float* __restrict__ fv) {
    int i = blockIdx.x * 256 + threadIdx.x;
    if (i < L_ * H_) {
        float s = zg[i] * rsqrtf(zv[i] + EPS_);
        g_zs[i] = s; g_zb[i] = zb[i] - zm[i] * s;
        float s2 = cg[i] * rsqrtf(cv[i] + EPS_);
        g_cs[i] = s2; g_cb[i] = cb[i] - cm[i] * s2;
    }
    if (i < O_) {
        float s = fg[i] * rsqrtf(fv[i] + EPS_);
        g_fs[i] = s; g_fb[i] = fb[i] - fm[i] * s;
    }
}

// ---------------- GEMM: C[M,N] = A[M,K] * B[N,K]^T  (tf32 mma.sync) ----------------
// CTA tile 128x128x32, 3-stage cp.async pipeline, 8 warps (2m x 4n), warp tile 64x32.
// Shared memory per stage: A 128x32 f32 (16KB) + B 128x32 f32 (16KB). XOR-swizzled
// in 16B chunks: chunk' = chunk ^ (row & 7) -> conflict-free ldmatrix & stores.

__device__ __forceinline__ void g_load_stage(uint32_t smemBase, int s, int kt,
                                             const float* __restrict__ A,
                                             const float* __restrict__ Bw,
                                             int K, int mBase, int nBase, int tid) {
    uint32_t aS = smemBase + (uint32_t)s * 32768u;
    uint32_t bS = aS + 16384u;
#pragma unroll
    for (int i = 0; i < 4; ++i) {
        int chunk = tid + (i << 8);             // 0..1023
        int row = chunk >> 3;
        int c = chunk & 7;
        const float* src = A + (size_t)(mBase + row) * (size_t)K + (size_t)(kt * 32 + (c << 2));
        uint32_t dst = aS + (uint32_t)((row << 7) + ((c ^ (row & 7)) << 4));
        asm volatile("cp.async.cg.shared.global [%0], [%1], 16;\n" :: "r"(dst), "l"(src) : "memory");
    }
#pragma unroll
    for (int i = 0; i < 4; ++i) {
        int chunk = tid + (i << 8);
        int row = chunk >> 3;
        int c = chunk & 7;
        const float* src = Bw + (size_t)(nBase + row) * (size_t)K + (size_t)(kt * 32 + (c << 2));
        uint32_t dst = bS + (uint32_t)((row << 7) + ((c ^ (row & 7)) << 4));
        asm volatile("cp.async.cg.shared.global [%0], [%1], 16;\n" :: "r"(dst), "l"(src) : "memory");
    }
}

template <bool FINAL>
__global__ void __launch_bounds__(256, 2)
gemm_kernel(int selA, int selB, int wOff, int K, int paramOff, float* __restrict__ outF) {
    extern __shared__ float smem[];
    const float* __restrict__ A = selA ? g_X : g_A0;
    const float* __restrict__ Bw = (selB == 0) ? g_W0 : ((selB == 1) ? (g_Wr + wOff) : g_Wf);

    const int tid  = threadIdx.x;
    const int lane = tid & 31;
    const int warp = tid >> 5;
    const int wm = warp & 1;       // 0..1  (m direction, 64 rows each)
    const int wn = warp >> 1;      // 0..3  (n direction, 32 cols each)
    const int mBase = blockIdx.y * 128;
    const int nBase = blockIdx.x * 128;

    uint32_t smemBase = (uint32_t)__cvta_generic_to_shared(smem);

    float acc[4][4][4];
#pragma unroll
    for (int mi = 0; mi < 4; ++mi)
#pragma unroll
        for (int ni = 0; ni < 4; ++ni)
#pragma unroll
            for (int e = 0; e < 4; ++e) acc[mi][ni][e] = 0.0f;

    const int NK = K >> 5;   // >= 14 always

    g_load_stage(smemBase, 0, 0, A, Bw, K, mBase, nBase, tid);
    asm volatile("cp.async.commit_group;\n" ::: "memory");
    g_load_stage(smemBase, 1, 1, A, Bw, K, mBase, nBase, tid);
    asm volatile("cp.async.commit_group;\n" ::: "memory");

    const int q = lane >> 3;      // 0..3 (ldmatrix sub-matrix index)
    const int r = lane & 7;

    for (int kt = 0; kt < NK; ++kt) {
        if (kt + 1 < NK) { asm volatile("cp.async.wait_group 1;\n" ::: "memory"); }
        else            { asm volatile("cp.async.wait_group 0;\n" ::: "memory"); }
        __syncthreads();

        if (kt + 2 < NK) {
            g_load_stage(smemBase, (kt + 2) % 3, kt + 2, A, Bw, K, mBase, nBase, tid);
            asm volatile("cp.async.commit_group;\n" ::: "memory");
        }

        uint32_t aS = smemBase + (uint32_t)((kt % 3) * 32768);
        uint32_t bS = aS + 16384u;

#pragma unroll
        for (int kk = 0; kk < 4; ++kk) {
            uint32_t af[4][4];
#pragma unroll
            for (int mi = 0; mi < 4; ++mi) {
                int m0 = wm * 64 + mi * 16;
                int mrow = m0 + r + ((q & 1) << 3);
                int ch = 2 * kk + (q >> 1);
                uint32_t addr = aS + (uint32_t)((mrow << 7) + ((ch ^ (mrow & 7)) << 4));
                asm volatile("ldmatrix.sync.aligned.m8n8.x4.shared.b16 {%0,%1,%2,%3}, [%4];\n"
                             : "=r"(af[mi][0]), "=r"(af[mi][1]), "=r"(af[mi][2]), "=r"(af[mi][3])
                             : "r"(addr));
            }
            uint32_t bf[4][2];
#pragma unroll
            for (int p = 0; p < 2; ++p) {
                int ni = p * 2 + (q >> 1);
                int nrow = wn * 32 + ni * 8 + r;
                int ch = 2 * kk + (q & 1);
                uint32_t addr = bS + (uint32_t)((nrow << 7) + ((ch ^ (nrow & 7)) << 4));
                asm volatile("ldmatrix.sync.aligned.m8n8.x4.shared.b16 {%0,%1,%2,%3}, [%4];\n"
                             : "=r"(bf[p * 2][0]), "=r"(bf[p * 2][1]),
                               "=r"(bf[p * 2 + 1][0]), "=r"(bf[p * 2 + 1][1])
                             : "r"(addr));
            }
#pragma unroll
            for (int mi = 0; mi < 4; ++mi)
#pragma unroll
                for (int ni = 0; ni < 4; ++ni) {
                    asm volatile(
                        "mma.sync.aligned.m16n8k8.row.col.f32.tf32.tf32.f32 "
                        "{%0,%1,%2,%3}, {%4,%5,%6,%7}, {%8,%9}, {%0,%1,%2,%3};\n"
                        : "+f"(acc[mi][ni][0]), "+f"(acc[mi][ni][1]),
                          "+f"(acc[mi][ni][2]), "+f"(acc[mi][ni][3])
                        : "r"(af[mi][0]), "r"(af[mi][1]), "r"(af[mi][2]), "r"(af[mi][3]),
                          "r"(bf[ni][0]), "r"(bf[ni][1]));
                }
        }
    }

    // ---------------- fused epilogue ----------------
    const int gg = lane >> 2;
    const int tt = lane & 3;
#pragma unroll
    for (int mi = 0; mi < 4; ++mi) {
#pragma unroll
        for (int ni = 0; ni < 4; ++ni) {
            int row = mBase + wm * 64 + mi * 16 + gg;
            int col = nBase + wn * 32 + ni * 8 + 2 * tt;
#pragma unroll
            for (int e = 0; e < 4; ++e) {
                int rr = row + ((e >= 2) ? 8 : 0);
                int cc = col + (e & 1);
                float v = acc[mi][ni][e];
                if (FINAL) {
                    if (cc < O_) outF[(size_t)rr * O_ + cc] = g_fs[cc] * v + g_fb[cc];
                } else {
                    if (cc < H_) {
                        float x = g_zs[paramOff + cc] * v + g_zb[paramOff + cc];
                        g_Z[(size_t)rr * H_ + cc] = 1.0f / (1.0f + __expf(-x));
                    } else {
                        int c2 = cc - H_;
                        float x = g_cs[paramOff + c2] * v + g_cb[paramOff + c2];
                        g_C[(size_t)rr * H_ + c2] = fmaxf(x, 0.0f);
                    }
                }
            }
        }
    }
}

// ---------------- recurrence scan: elementwise over (b,h), sequential in t ----------------
__global__ void scan_kernel() {
    int e = blockIdx.x * blockDim.x + threadIdx.x;   // 0..32767  (= b*H + h)
    float h = 0.0f;
    size_t idx = (size_t)e;
#pragma unroll 8
    for (int t = 0; t < T_; ++t) {
        float z = g_Z[idx];
        float c = g_C[idx];
        h = (1.0f - z) * c + z * h;
        g_X[idx] = tf32r(h);
        idx += (size_t)(B_ * H_);
    }
}

// ---------------- row-wise log_softmax over O=2000, in place ----------------
__global__ void lsm_kernel(float* __restrict__ out) {
    const int rrow = blockIdx.x;
    float* p = out + (size_t)rrow * O_;
    __shared__ float sm1[8];
    __shared__ float sm2[8];
    const int tid = threadIdx.x;

    float mx = -1e30f;
    for (int o = tid; o < O_; o += 256) mx = fmaxf(mx, p[o]);
#pragma unroll
    for (int off = 16; off; off >>= 1) mx = fmaxf(mx, __shfl_xor_sync(0xffffffffu, mx, off));
    if ((tid & 31) == 0) sm1[tid >> 5] = mx;
    __syncthreads();
    float bm = fmaxf(fmaxf(fmaxf(sm1[0], sm1[1]), fmaxf(sm1[2], sm1[3])),
                     fmaxf(fmaxf(sm1[4], sm1[5]), fmaxf(sm1[6], sm1[7])));

    float s = 0.0f;
    for (int o = tid; o < O_; o += 256) s += __expf(p[o] - bm);
#pragma unroll
    for (int off = 16; off; off >>= 1) s += __shfl_xor_sync(0xffffffffu, s, off);
    if ((tid & 31) == 0) sm2[tid >> 5] = s;
    __syncthreads();
    float bs = sm2[0] + sm2[1] + sm2[2] + sm2[3] + sm2[4] + sm2[5] + sm2[6] + sm2[7];

    float lse = bm + logf(bs);
    for (int o = tid; o < O_; o += 256) p[o] = p[o] - lse;
}

// ---------------- launch ----------------
extern "C" void kernel_launch(void* const* d_in, const int* in_sizes, int n_in,
                              void* d_out, int out_size) {
    (void)in_sizes; (void)n_in; (void)out_size;
    const float* xs    = (const float*)d_in[0];
    const float* w0    = (const float*)d_in[1];
    const float* wr    = (const float*)d_in[2];
    const float* bnz_g = (const float*)d_in[3];
    const float* bnz_b = (const float*)d_in[4];
    const float* bnz_m = (const float*)d_in[5];
    const float* bnz_v = (const float*)d_in[6];
    const float* bnc_g = (const float*)d_in[7];
    const float* bnc_b = (const float*)d_in[8];
    const float* bnc_m = (const float*)d_in[9];
    const float* bnc_v = (const float*)d_in[10];
    const float* wf    = (const float*)d_in[11];
    const float* bnf_g = (const float*)d_in[12];
    const float* bnf_b = (const float*)d_in[13];
    const float* bnf_m = (const float*)d_in[14];
    const float* bnf_v = (const float*)d_in[15];
    float* out = (float*)d_out;

    const int SMEM = 98304;   // 3 stages * 32KB
    cudaFuncSetAttribute(gemm_kernel<false>, cudaFuncAttributeMaxDynamicSharedMemorySize, SMEM);
    cudaFuncSetAttribute(gemm_kernel<true>,  cudaFuncAttributeMaxDynamicSharedMemorySize, SMEM);

    prep_x <<<(M_ * DP_ + 255) / 256, 256>>>(xs);
    prep_w0<<<(HH_ * DP_ + 255) / 256, 256>>>(w0);
    prep_wr<<<(3 * HH_ * H_ + 255) / 256, 256>>>(wr);
    prep_wf<<<(OP_ * H_ + 255) / 256, 256>>>(wf);
    prep_bn<<<16, 256>>>(bnz_g, bnz_b, bnz_m, bnz_v,
                         bnc_g, bnc_b, bnc_m, bnc_v,
                         bnf_g, bnf_b, bnf_m, bnf_v);

    dim3 grid(16, 200);   // N/128, M/128

    // layer 0: A = padded xs (K=448), B = padded w0
    gemm_kernel<false><<<grid, 256, SMEM>>>(0, 0, 0, DP_, 0, nullptr);
    scan_kernel<<<128, 256>>>();

    // layers 1..3: A = X (K=1024), B = wr[i-1]
    for (int i = 1; i < L_; ++i) {
        gemm_kernel<false><<<grid, 256, SMEM>>>(1, 1, (i - 1) * HH_ * H_, H_, i * H_, nullptr);
        scan_kernel<<<128, 256>>>();
    }

    // final: logits = X @ wf^T with fused BN, then log_softmax in place
    gemm_kernel<true><<<grid, 256, SMEM>>>(1, 2, 0, H_, 0, out);
    lsm_kernel<<<M_, 256>>>(out);
}

// round 14
// speedup vs baseline: 1.0006x; 1.0003x over previous
#include <cuda_runtime.h>
#include <cstdint>
#include <cstddef>

// Problem constants
#define T_   800
#define B_   32
#define D_   440
#define DP_  448      // D padded to multiple of 32
#define H_   1024
#define HH_  2048     // 2*H
#define L_   4
#define O_   2000
#define OP_  2048     // O padded to multiple of 128
#define M_   25600    // T*B
#define EPS_ 1e-5f

// ---------------- device-global scratch (allowed; zero-initialized) ----------------
__device__ float g_A0[M_ * DP_];          // padded+tf32-rounded xs          (45.9 MB)
__device__ float g_W0[HH_ * DP_];         // padded+rounded w0               ( 3.7 MB)
__device__ float g_Wr[3 * HH_ * H_];      // rounded wr                      (25.2 MB)
__device__ float g_Wf[OP_ * H_];          // rounded wf, rows >=2000 zero    ( 8.4 MB)
__device__ float g_Z[M_ * H_];            // sigmoid(BN(wz))                 (104.9 MB)
__device__ float g_C[M_ * H_];            // relu(BN(wc))                    (104.9 MB)
__device__ float g_X[M_ * H_];            // layer output (tf32-rounded)     (104.9 MB)
__device__ float g_zs[L_ * H_], g_zb[L_ * H_];
__device__ float g_cs[L_ * H_], g_cb[L_ * H_];
__device__ float g_fs[O_], g_fb[O_];

__device__ __forceinline__ float tf32r(float x) {
    uint32_t u;
    asm("cvt.rna.tf32.f32 %0, %1;" : "=r"(u) : "f"(x));
    return __uint_as_float(u);
}

// ---------------- prep kernels: pad + round-to-tf32 + BN fold ----------------
__global__ void prep_x(const float* __restrict__ xs) {
    int i = blockIdx.x * 256 + threadIdx.x;
    if (i >= M_ * DP_) return;
    int row = i / DP_, col = i - row * DP_;
    float v = (col < D_) ? xs[(size_t)row * D_ + col] : 0.0f;
    g_A0[i] = tf32r(v);
}
__global__ void prep_w0(const float* __restrict__ w) {
    int i = blockIdx.x * 256 + threadIdx.x;
    if (i >= HH_ * DP_) return;
    int row = i / DP_, col = i - row * DP_;
    float v = (col < D_) ? w[(size_t)row * D_ + col] : 0.0f;
    g_W0[i] = tf32r(v);
}
__global__ void prep_wr(const float* __restrict__ w) {
    int i = blockIdx.x * 256 + threadIdx.x;
    if (i >= 3 * HH_ * H_) return;
    g_Wr[i] = tf32r(w[i]);
}
__global__ void prep_wf(const float* __restrict__ w) {
    int i = blockIdx.x * 256 + threadIdx.x;
    if (i >= OP_ * H_) return;
    int row = i / H_, col = i - row * H_;
    g_Wf[i] = (row < O_) ? tf32r(w[(size_t)row * H_ + col]) : 0.0f;
}
__global__ void prep_bn(const float* __restrict__ zg, const float* __restrict__ zb,
                        const float* __restrict__ zm, const float* __restrict__ zv,
                        const float* __restrict__ cg, const float* __restrict__ cb,
                        const float* __restrict__ cm, const float* __restrict__ cv,
                        const float* __restrict__ fg, const float* __restrict__ fb,
                        const float* __restrict__ fm, const float* __restrict__ fv) {
    int i = blockIdx.x * 256 + threadIdx.x;
    if (i < L_ * H_) {
        float s = zg[i] * rsqrtf(zv[i] + EPS_);
        g_zs[i] = s; g_zb[i] = zb[i] - zm[i] * s;
        float s2 = cg[i] * rsqrtf(cv[i] + EPS_);
        g_cs[i] = s2; g_cb[i] = cb[i] - cm[i] * s2;
    }
    if (i < O_) {
        float s = fg[i] * rsqrtf(fv[i] + EPS_);
        g_fs[i] = s; g_fb[i] = fb[i] - fm[i] * s;
    }
}

// ---------------- GEMM: C[M,N] = A[M,K] * B[N,K]^T  (tf32 mma.sync) ----------------
// CTA tile 128x128x32, 3-stage cp.async pipeline, 8 warps (2m x 4n), warp tile 64x32.
// Shared memory per stage: A 128x32 f32 (16KB) + B 128x32 f32 (16KB). XOR-swizzled
// in 16B chunks: chunk' = chunk ^ (row & 7) -> conflict-free ldmatrix & stores.

__device__ __forceinline__ void g_load_stage(uint32_t smemBase, int s, int kt,
                                             const float* __restrict__ A,
                                             const float* __restrict__ Bw,
                                             int K, int mBase, int nBase, int tid) {
    uint32_t aS = smemBase + (uint32_t)s * 32768u;
    uint32_t bS = aS + 16384u;
#pragma unroll
    for (int i = 0; i < 4; ++i) {
        int chunk = tid + (i << 8);             // 0..1023
        int row = chunk >> 3;
        int c = chunk & 7;
        const float* src = A + (size_t)(mBase + row) * (size_t)K + (size_t)(kt * 32 + (c << 2));
        uint32_t dst = aS + (uint32_t)((row << 7) + ((c ^ (row & 7)) << 4));
        asm volatile("cp.async.cg.shared.global [%0], [%1], 16;\n" :: "r"(dst), "l"(src) : "memory");
    }
#pragma unroll
    for (int i = 0; i < 4; ++i) {
        int chunk = tid + (i << 8);
        int row = chunk >> 3;
        int c = chunk & 7;
        const float* src = Bw + (size_t)(nBase + row) * (size_t)K + (size_t)(kt * 32 + (c << 2));
        uint32_t dst = bS + (uint32_t)((row << 7) + ((c ^ (row & 7)) << 4));
        asm volatile("cp.async.cg.shared.global [%0], [%1], 16;\n" :: "r"(dst), "l"(src) : "memory");
    }
}

template <bool FINAL>
__global__ void __launch_bounds__(256, 2)
gemm_kernel(int selA, int selB, int wOff, int K, int paramOff, float* __restrict__ outF) {
    extern __shared__ float smem[];
    const float* __restrict__ A = selA ? g_X : g_A0;
    const float* __restrict__ Bw = (selB == 0) ? g_W0 : ((selB == 1) ? (g_Wr + wOff) : g_Wf);

    const int tid  = threadIdx.x;
    const int lane = tid & 31;
    const int warp = tid >> 5;
    const int wm = warp & 1;       // 0..1  (m direction, 64 rows each)
    const int wn = warp >> 1;      // 0..3  (n direction, 32 cols each)
    const int mBase = blockIdx.y * 128;
    const int nBase = blockIdx.x * 128;

    uint32_t smemBase = (uint32_t)__cvta_generic_to_shared(smem);

    float acc[4][4][4];
#pragma unroll
    for (int mi = 0; mi < 4; ++mi)
#pragma unroll
        for (int ni = 0; ni < 4; ++ni)
#pragma unroll
            for (int e = 0; e < 4; ++e) acc[mi][ni][e] = 0.0f;

    const int NK = K >> 5;   // >= 14 always

    g_load_stage(smemBase, 0, 0, A, Bw, K, mBase, nBase, tid);
    asm volatile("cp.async.commit_group;\n" ::: "memory");
    g_load_stage(smemBase, 1, 1, A, Bw, K, mBase, nBase, tid);
    asm volatile("cp.async.commit_group;\n" ::: "memory");

    const int q = lane >> 3;      // 0..3 (ldmatrix sub-matrix index)
    const int r = lane & 7;

    for (int kt = 0; kt < NK; ++kt) {
        if (kt + 1 < NK) { asm volatile("cp.async.wait_group 1;\n" ::: "memory"); }
        else            { asm volatile("cp.async.wait_group 0;\n" ::: "memory"); }
        __syncthreads();

        if (kt + 2 < NK) {
            g_load_stage(smemBase, (kt + 2) % 3, kt + 2, A, Bw, K, mBase, nBase, tid);
            asm volatile("cp.async.commit_group;\n" ::: "memory");
        }

        uint32_t aS = smemBase + (uint32_t)((kt % 3) * 32768);
        uint32_t bS = aS + 16384u;

#pragma unroll
        for (int kk = 0; kk < 4; ++kk) {
            uint32_t af[4][4];
#pragma unroll
            for (int mi = 0; mi < 4; ++mi) {
                int m0 = wm * 64 + mi * 16;
                int mrow = m0 + r + ((q & 1) << 3);
                int ch = 2 * kk + (q >> 1);
                uint32_t addr = aS + (uint32_t)((mrow << 7) + ((ch ^ (mrow & 7)) << 4));
                asm volatile("ldmatrix.sync.aligned.m8n8.x4.shared.b16 {%0,%1,%2,%3}, [%4];\n"
                             : "=r"(af[mi][0]), "=r"(af[mi][1]), "=r"(af[mi][2]), "=r"(af[mi][3])
                             : "r"(addr));
            }
            uint32_t bf[4][2];
#pragma unroll
            for (int p = 0; p < 2; ++p) {
                int ni = p * 2 + (q >> 1);
                int nrow = wn * 32 + ni * 8 + r;
                int ch = 2 * kk + (q & 1);
                uint32_t addr = bS + (uint32_t)((nrow << 7) + ((ch ^ (nrow & 7)) << 4));
                asm volatile("ldmatrix.sync.aligned.m8n8.x4.shared.b16 {%0,%1,%2,%3}, [%4];\n"
                             : "=r"(bf[p * 2][0]), "=r"(bf[p * 2][1]),
                               "=r"(bf[p * 2 + 1][0]), "=r"(bf[p * 2 + 1][1])
                             : "r"(addr));
            }
#pragma unroll
            for (int mi = 0; mi < 4; ++mi)
#pragma unroll
                for (int ni = 0; ni < 4; ++ni) {
                    asm volatile(
                        "mma.sync.aligned.m16n8k8.row.col.f32.tf32.tf32.f32 "
                        "{%0,%1,%2,%3}, {%4,%5,%6,%7}, {%8,%9}, {%0,%1,%2,%3};\n"
                        : "+f"(acc[mi][ni][0]), "+f"(acc[mi][ni][1]),
                          "+f"(acc[mi][ni][2]), "+f"(acc[mi][ni][3])
                        : "r"(af[mi][0]), "r"(af[mi][1]), "r"(af[mi][2]), "r"(af[mi][3]),
                          "r"(bf[ni][0]), "r"(bf[ni][1]));
                }
        }
    }

    // ---------------- fused epilogue ----------------
    const int gg = lane >> 2;
    const int tt = lane & 3;
#pragma unroll
    for (int mi = 0; mi < 4; ++mi) {
#pragma unroll
        for (int ni = 0; ni < 4; ++ni) {
            int row = mBase + wm * 64 + mi * 16 + gg;
            int col = nBase + wn * 32 + ni * 8 + 2 * tt;
#pragma unroll
            for (int e = 0; e < 4; ++e) {
                int rr = row + ((e >= 2) ? 8 : 0);
                int cc = col + (e & 1);
                float v = acc[mi][ni][e];
                if (FINAL) {
                    if (cc < O_) outF[(size_t)rr * O_ + cc] = g_fs[cc] * v + g_fb[cc];
                } else {
                    if (cc < H_) {
                        float x = g_zs[paramOff + cc] * v + g_zb[paramOff + cc];
                        g_Z[(size_t)rr * H_ + cc] = 1.0f / (1.0f + __expf(-x));
                    } else {
                        int c2 = cc - H_;
                        float x = g_cs[paramOff + c2] * v + g_cb[paramOff + c2];
                        g_C[(size_t)rr * H_ + c2] = fmaxf(x, 0.0f);
                    }
                }
            }
        }
    }
}

// ---------------- recurrence scan: elementwise over (b,h), sequential in t ----------------
__global__ void scan_kernel() {
    int e = blockIdx.x * blockDim.x + threadIdx.x;   // 0..32767  (= b*H + h)
    float h = 0.0f;
    size_t idx = (size_t)e;
#pragma unroll 8
    for (int t = 0; t < T_; ++t) {
        float z = g_Z[idx];
        float c = g_C[idx];
        h = (1.0f - z) * c + z * h;
        g_X[idx] = tf32r(h);
        idx += (size_t)(B_ * H_);
    }
}

// ---------------- row-wise log_softmax over O=2000, in place ----------------
__global__ void lsm_kernel(float* __restrict__ out) {
    const int rrow = blockIdx.x;
    float* p = out + (size_t)rrow * O_;
    __shared__ float sm1[8];
    __shared__ float sm2[8];
    const int tid = threadIdx.x;

    float mx = -1e30f;
    for (int o = tid; o < O_; o += 256) mx = fmaxf(mx, p[o]);
#pragma unroll
    for (int off = 16; off; off >>= 1) mx = fmaxf(mx, __shfl_xor_sync(0xffffffffu, mx, off));
    if ((tid & 31) == 0) sm1[tid >> 5] = mx;
    __syncthreads();
    float bm = fmaxf(fmaxf(fmaxf(sm1[0], sm1[1]), fmaxf(sm1[2], sm1[3])),
                     fmaxf(fmaxf(sm1[4], sm1[5]), fmaxf(sm1[6], sm1[7])));

    float s = 0.0f;
    for (int o = tid; o < O_; o += 256) s += __expf(p[o] - bm);
#pragma unroll
    for (int off = 16; off; off >>= 1) s += __shfl_xor_sync(0xffffffffu, s, off);
    if ((tid & 31) == 0) sm2[tid >> 5] = s;
    __syncthreads();
    float bs = sm2[0] + sm2[1] + sm2[2] + sm2[3] + sm2[4] + sm2[5] + sm2[6] + sm2[7];

    float lse = bm + logf(bs);
    for (int o = tid; o < O_; o += 256) p[o] = p[o] - lse;
}

// ---------------- launch ----------------
extern "C" void kernel_launch(void* const* d_in, const int* in_sizes, int n_in,
                              void* d_out, int out_size) {
    (void)in_sizes; (void)n_in; (void)out_size;
    const float* xs    = (const float*)d_in[0];
    const float* w0    = (const float*)d_in[1];
    const float* wr    = (const float*)d_in[2];
    const float* bnz_g = (const float*)d_in[3];
    const float* bnz_b = (const float*)d_in[4];
    const float* bnz_m = (const float*)d_in[5];
    const float* bnz_v = (const float*)d_in[6];
    const float* bnc_g = (const float*)d_in[7];
    const float* bnc_b = (const float*)d_in[8];
    const float* bnc_m = (const float*)d_in[9];
    const float* bnc_v = (const float*)d_in[10];
    const float* wf    = (const float*)d_in[11];
    const float* bnf_g = (const float*)d_in[12];
    const float* bnf_b = (const float*)d_in[13];
    const float* bnf_m = (const float*)d_in[14];
    const float* bnf_v = (const float*)d_in[15];
    float* out = (float*)d_out;

    const int SMEM = 98304;   // 3 stages * 32KB
    cudaFuncSetAttribute(gemm_kernel<false>, cudaFuncAttributeMaxDynamicSharedMemorySize, SMEM);
    cudaFuncSetAttribute(gemm_kernel<true>,  cudaFuncAttributeMaxDynamicSharedMemorySize, SMEM);

    prep_x <<<(M_ * DP_ + 255) / 256, 256>>>(xs);
    prep_w0<<<(HH_ * DP_ + 255) / 256, 256>>>(w0);
    prep_wr<<<(3 * HH_ * H_ + 255) / 256, 256>>>(wr);
    prep_wf<<<(OP_ * H_ + 255) / 256, 256>>>(wf);
    prep_bn<<<16, 256>>>(bnz_g, bnz_b, bnz_m, bnz_v,
                         bnc_g, bnc_b, bnc_m, bnc_v,
                         bnf_g, bnf_b, bnf_m, bnf_v);

    dim3 grid(16, 200);   // N/128, M/128

    // layer 0: A = padded xs (K=448), B = padded w0
    gemm_kernel<false><<<grid, 256, SMEM>>>(0, 0, 0, DP_, 0, nullptr);
    scan_kernel<<<128, 256>>>();

    // layers 1..3: A = X (K=1024), B = wr[i-1]
    for (int i = 1; i < L_; ++i) {
        gemm_kernel<false><<<grid, 256, SMEM>>>(1, 1, (i - 1) * HH_ * H_, H_, i * H_, nullptr);
        scan_kernel<<<128, 256>>>();
    }

    // final: logits = X @ wf^T with fused BN, then log_softmax in place
    gemm_kernel<true><<<grid, 256, SMEM>>>(1, 2, 0, H_, 0, out);
    lsm_kernel<<<M_, 256>>>(out);
}